// round 14
// baseline (speedup 1.0000x reference)
#include <cuda_runtime.h>
#include <cuda_fp16.h>
#include <cstdint>
#include <cstddef>

// ---------------------------------------------------------------------------
// Problem constants
// ---------------------------------------------------------------------------
#define BATCH   4096
#define NTOK    49
#define DIM     512
#define HEADS   16
#define HDIM    32
#define MROWS   (BATCH * NTOK)          // 200704 = 1568 * 128 exactly
#define BH      (BATCH * HEADS)         // 65536
#define QK_SZ   ((size_t)BH * NTOK * HDIM)   // 102,760,448 halfs

// fp16 scratch.  NOTE: device globals are zero-initialized at load; the
// V-token padding [49..64) is never written and therefore stays zero, and it
// only ever multiplies P=0 in the attention kernel.  g_k16 carries +512 halfs
// of tail padding because the attention kernel stages K rows [0,56) per bh.
__device__ __align__(16) __half g_q16[QK_SZ];                 // [bh][tok][32]
__device__ __align__(16) __half g_k16[QK_SZ + 512];           // [bh][tok][32]
__device__ __align__(16) __half g_vt16[(size_t)BH * HDIM * 64]; // [bh][d][tok64]
__device__ __align__(16) __half g_x16[(size_t)MROWS * DIM];
__device__ __align__(16) __half g_wt16[3 * DIM * DIM];
// padded bias with mask folded in: [h][64][56]  (fp32)
__device__ __align__(16) float g_bias[HEADS * 64 * 56];

// ---------------------------------------------------------------------------
// helpers
// ---------------------------------------------------------------------------
__device__ __forceinline__ void mma_f16(float& d0, float& d1, float& d2, float& d3,
                                        unsigned a0, unsigned a1, unsigned a2, unsigned a3,
                                        unsigned b0, unsigned b1) {
    asm volatile(
        "mma.sync.aligned.m16n8k16.row.col.f32.f16.f16.f32 "
        "{%0,%1,%2,%3}, {%4,%5,%6,%7}, {%8,%9}, {%0,%1,%2,%3};"
        : "+f"(d0), "+f"(d1), "+f"(d2), "+f"(d3)
        : "r"(a0), "r"(a1), "r"(a2), "r"(a3), "r"(b0), "r"(b1));
}

__device__ __forceinline__ void ldmx4(unsigned* r, uint32_t addr) {
    asm volatile("ldmatrix.sync.aligned.m8n8.x4.shared.b16 {%0,%1,%2,%3}, [%4];"
                 : "=r"(r[0]), "=r"(r[1]), "=r"(r[2]), "=r"(r[3]) : "r"(addr));
}

__device__ __forceinline__ uint32_t smem_u32(const void* p) {
    return (uint32_t)__cvta_generic_to_shared(p);
}

__device__ __forceinline__ void cp16cg(uint32_t s, const void* g) {
    asm volatile("cp.async.cg.shared.global [%0], [%1], 16;" :: "r"(s), "l"(g));
}

__device__ __forceinline__ unsigned packh2(float a, float b) {
    __half2 h = __floats2half2_rn(a, b);
    return *(unsigned*)&h;
}

// ---------------------------------------------------------------------------
// Kernel 1 (FUSED PROLOGUE): one launch does
//   [0, NCONV)            : convert X to fp16 (8 floats / thread)
//   [NCONV, NCONV+768)    : transpose W ([512,512] x3) to fp16, K-contig rows
//   [NCONV+768, +224)     : gather rel-pos bias into padded [16][64][56]
// ---------------------------------------------------------------------------
#define NCONV  ((int)(((size_t)MROWS * DIM) / 2048))   // 50176
#define NTRANS 768                                     // 16*16*3
#define NBIAS  224                                     // 57344/256
#define NPRO   (NCONV + NTRANS + NBIAS)

__global__ __launch_bounds__(256) void prologue(
    const float* __restrict__ X,
    const float* __restrict__ Wq, const float* __restrict__ Wk,
    const float* __restrict__ Wv,
    const float* __restrict__ table, const int* __restrict__ idx) {
    int blk = blockIdx.x;
    if (blk < NCONV) {
        // ---- convert X ----
        size_t i = ((size_t)blk * 256 + threadIdx.x) * 8;
        float4 a = *(const float4*)(X + i);
        float4 b = *(const float4*)(X + i + 4);
        __half2 h0 = __floats2half2_rn(a.x, a.y);
        __half2 h1 = __floats2half2_rn(a.z, a.w);
        __half2 h2 = __floats2half2_rn(b.x, b.y);
        __half2 h3 = __floats2half2_rn(b.z, b.w);
        uint4 o;
        o.x = *(unsigned*)&h0; o.y = *(unsigned*)&h1;
        o.z = *(unsigned*)&h2; o.w = *(unsigned*)&h3;
        *(uint4*)(g_x16 + i) = o;
    } else if (blk < NCONV + NTRANS) {
        // ---- transpose W (32x32 tile, 256 threads = 32x8) ----
        __shared__ float t[32][33];
        int id = blk - NCONV;
        int z = id >> 8;                 // 0..2
        int rem = id & 255;
        int bx = rem & 15, by = rem >> 4;
        const float* W = (z == 0) ? Wq : (z == 1) ? Wk : Wv;
        int tx = threadIdx.x & 31, ty = threadIdx.x >> 5;   // 32 x 8
#pragma unroll
        for (int j = 0; j < 4; j++) {
            int y = ty + j * 8;
            t[y][tx] = W[(by * 32 + y) * DIM + bx * 32 + tx];
        }
        __syncthreads();
#pragma unroll
        for (int j = 0; j < 4; j++) {
            int y = ty + j * 8;          // output row-within-tile
            float v = t[tx][y];
            g_wt16[(size_t)z * DIM * DIM + (size_t)(bx * 32 + y) * DIM
                   + by * 32 + tx] = __float2half_rn(v);
        }
    } else {
        // ---- bias gather ----
        int t = (blk - NCONV - NTRANS) * 256 + threadIdx.x;
        if (t >= HEADS * 64 * 56) return;
        int h = t / (64 * 56);
        int r = (t / 56) % 64;
        int c = t % 56;
        float v;
        if (c >= NTOK)      v = -1e30f;
        else if (r >= NTOK) v = 0.0f;
        else                v = table[idx[r * NTOK + c] * HEADS + h];
        g_bias[(h * 64 + r) * 56 + c] = v;
    }
}

// ---------------------------------------------------------------------------
// Kernel 2: QKV projection GEMM  [200704,512] x [512,1536]  (fp16 HMMA.16816)
//   R5 config (best measured): CTA 128x128, 256 threads, 8 warps 2(M)x4(N),
//   warp tile 64x32, k-chunk 64, 3-stage cp.async, one barrier per chunk.
//   Swizzle: 128B rows of 8 16B chunks; chunk' = chunk ^ (row & 7).
// ---------------------------------------------------------------------------
#define STGB 32768                      // A 16KB + B 16KB per stage
#define NSTG 3
#define GSMEM (NSTG * STGB)             // 98304

__global__ __launch_bounds__(256, 2) void gemm_qkv_f16(
    const float* __restrict__ bq, const float* __restrict__ bk,
    const float* __restrict__ bv) {
    extern __shared__ __align__(128) char sm[];
    uint32_t sbase = smem_u32(sm);
    int tid = threadIdx.x;
    int lane = tid & 31, wid = tid >> 5;
    int wm = wid >> 2, wn = wid & 3;
    int lg = lane >> 2, lt = lane & 3;

    int nBase = blockIdx.x * 128;       // 12 N-CTAs share one A M-tile (L2)
    int mBase = blockIdx.y * 128;
    int which = nBase >> 9;             // 0=Q 1=K 2=V
    int nLoc  = nBase & 511;
    const __half* Xs = g_x16 + (size_t)mBase * DIM;
    const __half* Ws = g_wt16 + (size_t)which * DIM * DIM + (size_t)nLoc * DIM;
    const float* bias = (which == 0) ? bq : (which == 1) ? bk : bv;

    float acc[4][4][4];
#pragma unroll
    for (int mt = 0; mt < 4; mt++)
#pragma unroll
        for (int nt = 0; nt < 4; nt++)
#pragma unroll
            for (int i = 0; i < 4; i++) acc[mt][nt][i] = 0.f;

    // one stage = 64 k-columns: A[128][64], B[128][64] fp16, 128B rows
    auto load_stage = [&](int buf, int kc) {
        uint32_t Ab = sbase + buf * STGB;
        uint32_t Bb = Ab + 16384;
#pragma unroll
        for (int i = 0; i < 4; i++) {
            int idx = i * 256 + tid;        // 0..1023
            int r = idx >> 3, c = idx & 7;
            uint32_t dst = r * 128 + ((uint32_t)(c ^ (r & 7))) * 16;
            cp16cg(Ab + dst, Xs + (size_t)r * DIM + kc * 64 + c * 8);
            cp16cg(Bb + dst, Ws + (size_t)r * DIM + kc * 64 + c * 8);
        }
        asm volatile("cp.async.commit_group;" ::: "memory");
    };

    load_stage(0, 0);
    load_stage(1, 1);

    int rA = wm * 64 + (lane & 15);
    int rB = wn * 32 + (lane & 15);
    int cc0 = (lane >> 4);
    int lsw = lane & 7;                 // row&7 == lane&7 for all our ldmatrix

#pragma unroll
    for (int kc = 0; kc < 8; kc++) {
        if (kc < 7) asm volatile("cp.async.wait_group 1;" ::: "memory");
        else        asm volatile("cp.async.wait_group 0;" ::: "memory");
        __syncthreads();
        if (kc + 2 < 8) load_stage((kc + 2) % NSTG, kc + 2);

        uint32_t Ab = sbase + (kc % NSTG) * STGB;
        uint32_t Bb = Ab + 16384;
#pragma unroll
        for (int ks = 0; ks < 4; ks++) {
            uint32_t chunk = (uint32_t)((2 * ks + cc0) ^ lsw);
            unsigned a[4][4];
#pragma unroll
            for (int mt = 0; mt < 4; mt++)
                ldmx4(a[mt], Ab + (rA + mt * 16) * 128 + chunk * 16);
            unsigned bf[2][4];
#pragma unroll
            for (int np = 0; np < 2; np++)
                ldmx4(bf[np], Bb + (rB + np * 16) * 128 + chunk * 16);
#pragma unroll
            for (int mt = 0; mt < 4; mt++) {
#pragma unroll
                for (int nt = 0; nt < 4; nt++) {
                    unsigned b0 = bf[nt >> 1][nt & 1];
                    unsigned b1 = bf[nt >> 1][(nt & 1) + 2];
                    mma_f16(acc[mt][nt][0], acc[mt][nt][1], acc[mt][nt][2], acc[mt][nt][3],
                            a[mt][0], a[mt][1], a[mt][2], a[mt][3], b0, b1);
                }
            }
        }
    }

    // epilogue: bias add + fp16 scatter.
    // Q/K -> [bh][tok][32]; V -> transposed [bh][d][64]
#pragma unroll
    for (int mt = 0; mt < 4; mt++) {
#pragma unroll
        for (int nt = 0; nt < 4; nt++) {
            int cc = nLoc + wn * 32 + nt * 8 + 2 * lt;   // column within matrix
            float bv0 = bias[cc], bv1 = bias[cc + 1];
            int h = cc >> 5, d = cc & 31;
            int r0 = mBase + wm * 64 + mt * 16 + lg;
            int r1 = r0 + 8;
            int b0i = r0 / NTOK, tok0 = r0 - b0i * NTOK;
            int b1i = r1 / NTOK, tok1 = r1 - b1i * NTOK;
            float v0 = acc[mt][nt][0] + bv0, v1 = acc[mt][nt][1] + bv1;
            float v2 = acc[mt][nt][2] + bv0, v3 = acc[mt][nt][3] + bv1;
            if (which < 2) {
                __half* base = (which == 0) ? g_q16 : g_k16;
                *(unsigned*)(base + ((size_t)(b0i * HEADS + h) * NTOK + tok0) * HDIM + d)
                    = packh2(v0, v1);
                *(unsigned*)(base + ((size_t)(b1i * HEADS + h) * NTOK + tok1) * HDIM + d)
                    = packh2(v2, v3);
            } else {
                __half* vt0 = g_vt16 + (size_t)(b0i * HEADS + h) * (HDIM * 64);
                __half* vt1 = g_vt16 + (size_t)(b1i * HEADS + h) * (HDIM * 64);
                vt0[d * 64 + tok0]       = __float2half_rn(v0);
                vt0[(d + 1) * 64 + tok0] = __float2half_rn(v1);
                vt1[d * 64 + tok1]       = __float2half_rn(v2);
                vt1[(d + 1) * 64 + tok1] = __float2half_rn(v3);
            }
        }
    }
}

// ---------------------------------------------------------------------------
// Kernel 3: attention (R8 structure, best measured) with a forced occupancy
//   floor: __launch_bounds__(128, 5) caps regs at 102 -> 5 CTAs/SM (smem
//   allows 6).  1 warp = 1 (window, head), 4 warps/CTA.  K/V staged to
//   per-warp smem via cp.async; fragments via ldmatrix.x4 (K stride 80B,
//   Vt 144B, conflict-free).  Q direct gmem.  S C-layout == P A-layout.
// ---------------------------------------------------------------------------
#define KS_STRIDE 80                    // 56 rows -> 4480 B
#define VS_STRIDE 144                   // 32 rows -> 4608 B
#define WSMEM (56 * KS_STRIDE + 32 * VS_STRIDE)   // 9088 B per bh

__global__ __launch_bounds__(128, 5) void attn_kernel(float* __restrict__ out) {
    __shared__ __align__(128) char smk[4 * WSMEM];
    int lane = threadIdx.x & 31, wid = threadIdx.x >> 5;
    int bh = blockIdx.x * 4 + wid;
    int b = bh >> 4, h = bh & 15;

    const __half* Q  = g_q16 + (size_t)bh * (NTOK * HDIM);
    const __half* Kg = g_k16 + (size_t)bh * (NTOK * HDIM);
    const __half* Vg = g_vt16 + (size_t)bh * (HDIM * 64);
    const float* biasH = g_bias + h * 64 * 56;
    const float scale = 0.17677669529663687f;   // 1/sqrt(32)

    uint32_t wbase = smem_u32(smk) + wid * WSMEM;
    uint32_t Ks = wbase;
    uint32_t Vs = wbase + 56 * KS_STRIDE;

    // stage K rows [0,56) (rows 49..55 garbage -> masked by -1e30 bias) and
    // full Vt [32][64] (token pad zero in gmem).  16B chunks, 15 per lane.
#pragma unroll
    for (int i = 0; i < 7; i++) {       // K: 224 chunks (56 rows x 4)
        int idx = i * 32 + lane;
        cp16cg(Ks + (idx >> 2) * KS_STRIDE + (idx & 3) * 16,
               Kg + (idx >> 2) * HDIM + (idx & 3) * 8);
    }
#pragma unroll
    for (int i = 0; i < 8; i++) {       // V: 256 chunks (32 rows x 8)
        int idx = i * 32 + lane;
        cp16cg(Vs + (idx >> 3) * VS_STRIDE + (idx & 7) * 16,
               Vg + (idx >> 3) * 64 + (idx & 7) * 8);
    }
    asm volatile("cp.async.wait_all;" ::: "memory");
    __syncthreads();

    int lg = lane >> 2;    // 0..7
    int lt = lane & 3;     // 0..3
    int cb = 2 * lt;
    int l7 = lane & 7, l3h = lane >> 3;       // ldmatrix addressing

    // K fragments via ldmatrix: kb[nt][q] = K[nt*8+lg][8q+2lt .. +1]
    unsigned kb[7][4];
#pragma unroll
    for (int nt = 0; nt < 7; nt++)
        ldmx4(kb[nt], Ks + (nt * 8 + l7) * KS_STRIDE + l3h * 16);

    // V fragments via ldmatrix: vb[dn][c] = Vt[dn*8+lg][8c+2lt .. +1]
    unsigned vb[4][8];
#pragma unroll
    for (int dn = 0; dn < 4; dn++) {
        ldmx4(&vb[dn][0], Vs + (dn * 8 + l7) * VS_STRIDE + l3h * 16);
        ldmx4(&vb[dn][4], Vs + (dn * 8 + l7) * VS_STRIDE + l3h * 16 + 64);
    }

#pragma unroll
    for (int mt = 0; mt < 4; mt++) {
        int r0 = mt * 16 + lg;
        int r1 = r0 + 8;
        bool r0v = (r0 < NTOK), r1v = (r1 < NTOK);

        // prefetch bias rows (fp32, L2-resident) ahead of the mma block
        float2 bz0[7], bz1[7];
#pragma unroll
        for (int nt = 0; nt < 7; nt++) {
            bz0[nt] = *(const float2*)(biasH + r0 * 56 + nt * 8 + cb);
            bz1[nt] = *(const float2*)(biasH + r1 * 56 + nt * 8 + cb);
        }

        // Q fragments (direct gmem, read-once)
        unsigned qa[2][4];
#pragma unroll
        for (int kk = 0; kk < 2; kk++) {
            const __half* q0 = Q + r0 * HDIM + 16 * kk + 2 * lt;
            const __half* q1 = Q + r1 * HDIM + 16 * kk + 2 * lt;
            qa[kk][0] = r0v ? *(const unsigned*)q0 : 0u;
            qa[kk][1] = r1v ? *(const unsigned*)q1 : 0u;
            qa[kk][2] = r0v ? *(const unsigned*)(q0 + 8) : 0u;
            qa[kk][3] = r1v ? *(const unsigned*)(q1 + 8) : 0u;
        }

        float sc[7][4];
#pragma unroll
        for (int nt = 0; nt < 7; nt++)
#pragma unroll
            for (int i = 0; i < 4; i++) sc[nt][i] = 0.f;

        // S = Q K^T
#pragma unroll
        for (int nt = 0; nt < 7; nt++) {
            mma_f16(sc[nt][0], sc[nt][1], sc[nt][2], sc[nt][3],
                    qa[0][0], qa[0][1], qa[0][2], qa[0][3], kb[nt][0], kb[nt][1]);
            mma_f16(sc[nt][0], sc[nt][1], sc[nt][2], sc[nt][3],
                    qa[1][0], qa[1][1], qa[1][2], qa[1][3], kb[nt][2], kb[nt][3]);
        }

        // scale + bias (mask folded into bias)
#pragma unroll
        for (int nt = 0; nt < 7; nt++) {
            sc[nt][0] = sc[nt][0] * scale + bz0[nt].x;
            sc[nt][1] = sc[nt][1] * scale + bz0[nt].y;
            sc[nt][2] = sc[nt][2] * scale + bz1[nt].x;
            sc[nt][3] = sc[nt][3] * scale + bz1[nt].y;
        }

        // softmax (rows r0, r1)
        float m0 = -1e30f, m1 = -1e30f;
#pragma unroll
        for (int nt = 0; nt < 7; nt++) {
            m0 = fmaxf(m0, fmaxf(sc[nt][0], sc[nt][1]));
            m1 = fmaxf(m1, fmaxf(sc[nt][2], sc[nt][3]));
        }
        m0 = fmaxf(m0, __shfl_xor_sync(0xffffffffu, m0, 1));
        m0 = fmaxf(m0, __shfl_xor_sync(0xffffffffu, m0, 2));
        m1 = fmaxf(m1, __shfl_xor_sync(0xffffffffu, m1, 1));
        m1 = fmaxf(m1, __shfl_xor_sync(0xffffffffu, m1, 2));

        float rs0 = 0.f, rs1 = 0.f;
#pragma unroll
        for (int nt = 0; nt < 7; nt++) {
            sc[nt][0] = __expf(sc[nt][0] - m0); rs0 += sc[nt][0];
            sc[nt][1] = __expf(sc[nt][1] - m0); rs0 += sc[nt][1];
            sc[nt][2] = __expf(sc[nt][2] - m1); rs1 += sc[nt][2];
            sc[nt][3] = __expf(sc[nt][3] - m1); rs1 += sc[nt][3];
        }
        rs0 += __shfl_xor_sync(0xffffffffu, rs0, 1);
        rs0 += __shfl_xor_sync(0xffffffffu, rs0, 2);
        rs1 += __shfl_xor_sync(0xffffffffu, rs1, 1);
        rs1 += __shfl_xor_sync(0xffffffffu, rs1, 2);
        float inv0 = __fdividef(1.f, rs0);
        float inv1 = __fdividef(1.f, rs1);

        // pack P to fp16 A-fragments (C-layout == A-layout identity)
        unsigned pa0[8], pa1[8];
#pragma unroll
        for (int nt = 0; nt < 7; nt++) {
            pa0[nt] = packh2(sc[nt][0], sc[nt][1]);
            pa1[nt] = packh2(sc[nt][2], sc[nt][3]);
        }
        pa0[7] = 0u; pa1[7] = 0u;

        // O = P V   (4 k16 token tiles x 4 n8 dim tiles)
        float oa[4][4];
#pragma unroll
        for (int nt = 0; nt < 4; nt++)
#pragma unroll
            for (int i = 0; i < 4; i++) oa[nt][i] = 0.f;

#pragma unroll
        for (int kt = 0; kt < 4; kt++) {
            unsigned a0 = pa0[2 * kt],     a2 = pa0[2 * kt + 1];
            unsigned a1 = pa1[2 * kt],     a3 = pa1[2 * kt + 1];
#pragma unroll
            for (int dn = 0; dn < 4; dn++) {
                mma_f16(oa[dn][0], oa[dn][1], oa[dn][2], oa[dn][3],
                        a0, a1, a2, a3, vb[dn][2 * kt], vb[dn][2 * kt + 1]);
            }
        }

        // store (normalize by rowsum)
#pragma unroll
        for (int nt = 0; nt < 4; nt++) {
            int col = h * HDIM + nt * 8 + cb;
            if (r0v) {
                float* o = out + ((size_t)b * NTOK + r0) * DIM + col;
                o[0] = oa[nt][0] * inv0;
                o[1] = oa[nt][1] * inv0;
            }
            if (r1v) {
                float* o = out + ((size_t)b * NTOK + r1) * DIM + col;
                o[0] = oa[nt][2] * inv1;
                o[1] = oa[nt][3] * inv1;
            }
        }
    }
}

// ---------------------------------------------------------------------------
// launch
// ---------------------------------------------------------------------------
extern "C" void kernel_launch(void* const* d_in, const int* in_sizes, int n_in,
                              void* d_out, int out_size) {
    const float* X     = (const float*)d_in[0];
    const float* Wq    = (const float*)d_in[1];
    const float* bq    = (const float*)d_in[2];
    const float* Wk    = (const float*)d_in[3];
    const float* bk    = (const float*)d_in[4];
    const float* Wv    = (const float*)d_in[5];
    const float* bv    = (const float*)d_in[6];
    const float* table = (const float*)d_in[7];
    const int*   idx   = (const int*)d_in[8];
    float* out = (float*)d_out;

    cudaFuncSetAttribute(gemm_qkv_f16, cudaFuncAttributeMaxDynamicSharedMemorySize,
                         GSMEM);

    prologue<<<NPRO, 256>>>(X, Wq, Wk, Wv, table, idx);
    gemm_qkv_f16<<<dim3((3 * DIM) / 128, MROWS / 128), 256, GSMEM>>>(bq, bk, bv);
    attn_kernel<<<(BATCH * HEADS) / 4, 128>>>(out);
}

// round 15
// speedup vs baseline: 1.0461x; 1.0461x over previous
#include <cuda_runtime.h>
#include <cuda_fp16.h>
#include <cstdint>
#include <cstddef>

// ---------------------------------------------------------------------------
// Problem constants
// ---------------------------------------------------------------------------
#define BATCH   4096
#define NTOK    49
#define DIM     512
#define HEADS   16
#define HDIM    32
#define MROWS   (BATCH * NTOK)          // 200704 = 1568 * 128 exactly
#define BH      (BATCH * HEADS)         // 65536
#define QK_SZ   ((size_t)BH * NTOK * HDIM)   // 102,760,448 halfs

// fp16 scratch.  NOTE: device globals are zero-initialized at load; the
// V-token padding [49..64) is never written and therefore stays zero, and it
// only ever multiplies P=0 in the attention kernel.  g_k16 carries +512 halfs
// of tail padding because the attention kernel stages K rows [0,56) per bh.
__device__ __align__(16) __half g_q16[QK_SZ];                 // [bh][tok][32]
__device__ __align__(16) __half g_k16[QK_SZ + 512];           // [bh][tok][32]
__device__ __align__(16) __half g_vt16[(size_t)BH * HDIM * 64]; // [bh][d][tok64]
__device__ __align__(16) __half g_x16[(size_t)MROWS * DIM];
__device__ __align__(16) __half g_wt16[3 * DIM * DIM];
// padded bias with mask folded in: [h][64][56]  (fp32)
__device__ __align__(16) float g_bias[HEADS * 64 * 56];

// ---------------------------------------------------------------------------
// helpers
// ---------------------------------------------------------------------------
__device__ __forceinline__ void mma_f16(float& d0, float& d1, float& d2, float& d3,
                                        unsigned a0, unsigned a1, unsigned a2, unsigned a3,
                                        unsigned b0, unsigned b1) {
    asm volatile(
        "mma.sync.aligned.m16n8k16.row.col.f32.f16.f16.f32 "
        "{%0,%1,%2,%3}, {%4,%5,%6,%7}, {%8,%9}, {%0,%1,%2,%3};"
        : "+f"(d0), "+f"(d1), "+f"(d2), "+f"(d3)
        : "r"(a0), "r"(a1), "r"(a2), "r"(a3), "r"(b0), "r"(b1));
}

__device__ __forceinline__ void ldmx4(unsigned* r, uint32_t addr) {
    asm volatile("ldmatrix.sync.aligned.m8n8.x4.shared.b16 {%0,%1,%2,%3}, [%4];"
                 : "=r"(r[0]), "=r"(r[1]), "=r"(r[2]), "=r"(r[3]) : "r"(addr));
}

__device__ __forceinline__ uint32_t smem_u32(const void* p) {
    return (uint32_t)__cvta_generic_to_shared(p);
}

__device__ __forceinline__ void cp16cg(uint32_t s, const void* g) {
    asm volatile("cp.async.cg.shared.global [%0], [%1], 16;" :: "r"(s), "l"(g));
}

__device__ __forceinline__ unsigned packh2(float a, float b) {
    __half2 h = __floats2half2_rn(a, b);
    return *(unsigned*)&h;
}

// ---------------------------------------------------------------------------
// Kernel 1 (FUSED PROLOGUE): one launch does
//   [0, NCONV)            : convert X to fp16 (8 floats / thread)
//   [NCONV, NCONV+768)    : transpose W ([512,512] x3) to fp16, K-contig rows
//   [NCONV+768, +224)     : gather rel-pos bias into padded [16][64][56]
// ---------------------------------------------------------------------------
#define NCONV  ((int)(((size_t)MROWS * DIM) / 2048))   // 50176
#define NTRANS 768                                     // 16*16*3
#define NBIAS  224                                     // 57344/256
#define NPRO   (NCONV + NTRANS + NBIAS)

__global__ __launch_bounds__(256) void prologue(
    const float* __restrict__ X,
    const float* __restrict__ Wq, const float* __restrict__ Wk,
    const float* __restrict__ Wv,
    const float* __restrict__ table, const int* __restrict__ idx) {
    int blk = blockIdx.x;
    if (blk < NCONV) {
        // ---- convert X ----
        size_t i = ((size_t)blk * 256 + threadIdx.x) * 8;
        float4 a = *(const float4*)(X + i);
        float4 b = *(const float4*)(X + i + 4);
        __half2 h0 = __floats2half2_rn(a.x, a.y);
        __half2 h1 = __floats2half2_rn(a.z, a.w);
        __half2 h2 = __floats2half2_rn(b.x, b.y);
        __half2 h3 = __floats2half2_rn(b.z, b.w);
        uint4 o;
        o.x = *(unsigned*)&h0; o.y = *(unsigned*)&h1;
        o.z = *(unsigned*)&h2; o.w = *(unsigned*)&h3;
        *(uint4*)(g_x16 + i) = o;
    } else if (blk < NCONV + NTRANS) {
        // ---- transpose W (32x32 tile, 256 threads = 32x8) ----
        __shared__ float t[32][33];
        int id = blk - NCONV;
        int z = id >> 8;                 // 0..2
        int rem = id & 255;
        int bx = rem & 15, by = rem >> 4;
        const float* W = (z == 0) ? Wq : (z == 1) ? Wk : Wv;
        int tx = threadIdx.x & 31, ty = threadIdx.x >> 5;   // 32 x 8
#pragma unroll
        for (int j = 0; j < 4; j++) {
            int y = ty + j * 8;
            t[y][tx] = W[(by * 32 + y) * DIM + bx * 32 + tx];
        }
        __syncthreads();
#pragma unroll
        for (int j = 0; j < 4; j++) {
            int y = ty + j * 8;          // output row-within-tile
            float v = t[tx][y];
            g_wt16[(size_t)z * DIM * DIM + (size_t)(bx * 32 + y) * DIM
                   + by * 32 + tx] = __float2half_rn(v);
        }
    } else {
        // ---- bias gather ----
        int t = (blk - NCONV - NTRANS) * 256 + threadIdx.x;
        if (t >= HEADS * 64 * 56) return;
        int h = t / (64 * 56);
        int r = (t / 56) % 64;
        int c = t % 56;
        float v;
        if (c >= NTOK)      v = -1e30f;
        else if (r >= NTOK) v = 0.0f;
        else                v = table[idx[r * NTOK + c] * HEADS + h];
        g_bias[(h * 64 + r) * 56 + c] = v;
    }
}

// ---------------------------------------------------------------------------
// Kernel 2: QKV projection GEMM  [200704,512] x [512,1536]  (fp16 HMMA.16816)
//   R5 config (best measured): CTA 128x128, 256 threads, 8 warps 2(M)x4(N),
//   warp tile 64x32, k-chunk 64, 3-stage cp.async, one barrier per chunk.
//   Swizzle: 128B rows of 8 16B chunks; chunk' = chunk ^ (row & 7).
// ---------------------------------------------------------------------------
#define STGB 32768                      // A 16KB + B 16KB per stage
#define NSTG 3
#define GSMEM (NSTG * STGB)             // 98304

__global__ __launch_bounds__(256, 2) void gemm_qkv_f16(
    const float* __restrict__ bq, const float* __restrict__ bk,
    const float* __restrict__ bv) {
    extern __shared__ __align__(128) char sm[];
    uint32_t sbase = smem_u32(sm);
    int tid = threadIdx.x;
    int lane = tid & 31, wid = tid >> 5;
    int wm = wid >> 2, wn = wid & 3;
    int lg = lane >> 2, lt = lane & 3;

    int nBase = blockIdx.x * 128;       // 12 N-CTAs share one A M-tile (L2)
    int mBase = blockIdx.y * 128;
    int which = nBase >> 9;             // 0=Q 1=K 2=V
    int nLoc  = nBase & 511;
    const __half* Xs = g_x16 + (size_t)mBase * DIM;
    const __half* Ws = g_wt16 + (size_t)which * DIM * DIM + (size_t)nLoc * DIM;
    const float* bias = (which == 0) ? bq : (which == 1) ? bk : bv;

    float acc[4][4][4];
#pragma unroll
    for (int mt = 0; mt < 4; mt++)
#pragma unroll
        for (int nt = 0; nt < 4; nt++)
#pragma unroll
            for (int i = 0; i < 4; i++) acc[mt][nt][i] = 0.f;

    // one stage = 64 k-columns: A[128][64], B[128][64] fp16, 128B rows
    auto load_stage = [&](int buf, int kc) {
        uint32_t Ab = sbase + buf * STGB;
        uint32_t Bb = Ab + 16384;
#pragma unroll
        for (int i = 0; i < 4; i++) {
            int idx = i * 256 + tid;        // 0..1023
            int r = idx >> 3, c = idx & 7;
            uint32_t dst = r * 128 + ((uint32_t)(c ^ (r & 7))) * 16;
            cp16cg(Ab + dst, Xs + (size_t)r * DIM + kc * 64 + c * 8);
            cp16cg(Bb + dst, Ws + (size_t)r * DIM + kc * 64 + c * 8);
        }
        asm volatile("cp.async.commit_group;" ::: "memory");
    };

    load_stage(0, 0);
    load_stage(1, 1);

    int rA = wm * 64 + (lane & 15);
    int rB = wn * 32 + (lane & 15);
    int cc0 = (lane >> 4);
    int lsw = lane & 7;                 // row&7 == lane&7 for all our ldmatrix

#pragma unroll
    for (int kc = 0; kc < 8; kc++) {
        if (kc < 7) asm volatile("cp.async.wait_group 1;" ::: "memory");
        else        asm volatile("cp.async.wait_group 0;" ::: "memory");
        __syncthreads();
        if (kc + 2 < 8) load_stage((kc + 2) % NSTG, kc + 2);

        uint32_t Ab = sbase + (kc % NSTG) * STGB;
        uint32_t Bb = Ab + 16384;
#pragma unroll
        for (int ks = 0; ks < 4; ks++) {
            uint32_t chunk = (uint32_t)((2 * ks + cc0) ^ lsw);
            unsigned a[4][4];
#pragma unroll
            for (int mt = 0; mt < 4; mt++)
                ldmx4(a[mt], Ab + (rA + mt * 16) * 128 + chunk * 16);
            unsigned bf[2][4];
#pragma unroll
            for (int np = 0; np < 2; np++)
                ldmx4(bf[np], Bb + (rB + np * 16) * 128 + chunk * 16);
#pragma unroll
            for (int mt = 0; mt < 4; mt++) {
#pragma unroll
                for (int nt = 0; nt < 4; nt++) {
                    unsigned b0 = bf[nt >> 1][nt & 1];
                    unsigned b1 = bf[nt >> 1][(nt & 1) + 2];
                    mma_f16(acc[mt][nt][0], acc[mt][nt][1], acc[mt][nt][2], acc[mt][nt][3],
                            a[mt][0], a[mt][1], a[mt][2], a[mt][3], b0, b1);
                }
            }
        }
    }

    // epilogue: bias add + fp16 scatter.
    // Q/K -> [bh][tok][32]; V -> transposed [bh][d][64]
#pragma unroll
    for (int mt = 0; mt < 4; mt++) {
#pragma unroll
        for (int nt = 0; nt < 4; nt++) {
            int cc = nLoc + wn * 32 + nt * 8 + 2 * lt;   // column within matrix
            float bv0 = bias[cc], bv1 = bias[cc + 1];
            int h = cc >> 5, d = cc & 31;
            int r0 = mBase + wm * 64 + mt * 16 + lg;
            int r1 = r0 + 8;
            int b0i = r0 / NTOK, tok0 = r0 - b0i * NTOK;
            int b1i = r1 / NTOK, tok1 = r1 - b1i * NTOK;
            float v0 = acc[mt][nt][0] + bv0, v1 = acc[mt][nt][1] + bv1;
            float v2 = acc[mt][nt][2] + bv0, v3 = acc[mt][nt][3] + bv1;
            if (which < 2) {
                __half* base = (which == 0) ? g_q16 : g_k16;
                *(unsigned*)(base + ((size_t)(b0i * HEADS + h) * NTOK + tok0) * HDIM + d)
                    = packh2(v0, v1);
                *(unsigned*)(base + ((size_t)(b1i * HEADS + h) * NTOK + tok1) * HDIM + d)
                    = packh2(v2, v3);
            } else {
                __half* vt0 = g_vt16 + (size_t)(b0i * HEADS + h) * (HDIM * 64);
                __half* vt1 = g_vt16 + (size_t)(b1i * HEADS + h) * (HDIM * 64);
                vt0[d * 64 + tok0]       = __float2half_rn(v0);
                vt0[(d + 1) * 64 + tok0] = __float2half_rn(v1);
                vt1[d * 64 + tok1]       = __float2half_rn(v2);
                vt1[(d + 1) * 64 + tok1] = __float2half_rn(v3);
            }
        }
    }
}

// ---------------------------------------------------------------------------
// Kernel 3: attention (R8 structure, best measured; unconstrained regs).
//   1 warp = 1 (window, head), 4 warps/CTA.  K/V staged to per-warp smem via
//   cp.async; fragments via ldmatrix.x4 (K stride 80B, Vt 144B, conflict-
//   free).  Q direct gmem loads.  S C-layout == P A-layout.
// ---------------------------------------------------------------------------
#define KS_STRIDE 80                    // 56 rows -> 4480 B
#define VS_STRIDE 144                   // 32 rows -> 4608 B
#define WSMEM (56 * KS_STRIDE + 32 * VS_STRIDE)   // 9088 B per bh

__global__ __launch_bounds__(128) void attn_kernel(float* __restrict__ out) {
    __shared__ __align__(128) char smk[4 * WSMEM];
    int lane = threadIdx.x & 31, wid = threadIdx.x >> 5;
    int bh = blockIdx.x * 4 + wid;
    int b = bh >> 4, h = bh & 15;

    const __half* Q  = g_q16 + (size_t)bh * (NTOK * HDIM);
    const __half* Kg = g_k16 + (size_t)bh * (NTOK * HDIM);
    const __half* Vg = g_vt16 + (size_t)bh * (HDIM * 64);
    const float* biasH = g_bias + h * 64 * 56;
    const float scale = 0.17677669529663687f;   // 1/sqrt(32)

    uint32_t wbase = smem_u32(smk) + wid * WSMEM;
    uint32_t Ks = wbase;
    uint32_t Vs = wbase + 56 * KS_STRIDE;

    // stage K rows [0,56) (rows 49..55 garbage -> masked by -1e30 bias) and
    // full Vt [32][64] (token pad zero in gmem).  16B chunks, 15 per lane.
#pragma unroll
    for (int i = 0; i < 7; i++) {       // K: 224 chunks (56 rows x 4)
        int idx = i * 32 + lane;
        cp16cg(Ks + (idx >> 2) * KS_STRIDE + (idx & 3) * 16,
               Kg + (idx >> 2) * HDIM + (idx & 3) * 8);
    }
#pragma unroll
    for (int i = 0; i < 8; i++) {       // V: 256 chunks (32 rows x 8)
        int idx = i * 32 + lane;
        cp16cg(Vs + (idx >> 3) * VS_STRIDE + (idx & 7) * 16,
               Vg + (idx >> 3) * 64 + (idx & 7) * 8);
    }
    asm volatile("cp.async.wait_all;" ::: "memory");
    __syncthreads();

    int lg = lane >> 2;    // 0..7
    int lt = lane & 3;     // 0..3
    int cb = 2 * lt;
    int l7 = lane & 7, l3h = lane >> 3;       // ldmatrix addressing

    // K fragments via ldmatrix: kb[nt][q] = K[nt*8+lg][8q+2lt .. +1]
    unsigned kb[7][4];
#pragma unroll
    for (int nt = 0; nt < 7; nt++)
        ldmx4(kb[nt], Ks + (nt * 8 + l7) * KS_STRIDE + l3h * 16);

    // V fragments via ldmatrix: vb[dn][c] = Vt[dn*8+lg][8c+2lt .. +1]
    unsigned vb[4][8];
#pragma unroll
    for (int dn = 0; dn < 4; dn++) {
        ldmx4(&vb[dn][0], Vs + (dn * 8 + l7) * VS_STRIDE + l3h * 16);
        ldmx4(&vb[dn][4], Vs + (dn * 8 + l7) * VS_STRIDE + l3h * 16 + 64);
    }

#pragma unroll
    for (int mt = 0; mt < 4; mt++) {
        int r0 = mt * 16 + lg;
        int r1 = r0 + 8;
        bool r0v = (r0 < NTOK), r1v = (r1 < NTOK);

        // prefetch bias rows (fp32, L2-resident) ahead of the mma block
        float2 bz0[7], bz1[7];
#pragma unroll
        for (int nt = 0; nt < 7; nt++) {
            bz0[nt] = *(const float2*)(biasH + r0 * 56 + nt * 8 + cb);
            bz1[nt] = *(const float2*)(biasH + r1 * 56 + nt * 8 + cb);
        }

        // Q fragments (direct gmem, read-once)
        unsigned qa[2][4];
#pragma unroll
        for (int kk = 0; kk < 2; kk++) {
            const __half* q0 = Q + r0 * HDIM + 16 * kk + 2 * lt;
            const __half* q1 = Q + r1 * HDIM + 16 * kk + 2 * lt;
            qa[kk][0] = r0v ? *(const unsigned*)q0 : 0u;
            qa[kk][1] = r1v ? *(const unsigned*)q1 : 0u;
            qa[kk][2] = r0v ? *(const unsigned*)(q0 + 8) : 0u;
            qa[kk][3] = r1v ? *(const unsigned*)(q1 + 8) : 0u;
        }

        float sc[7][4];
#pragma unroll
        for (int nt = 0; nt < 7; nt++)
#pragma unroll
            for (int i = 0; i < 4; i++) sc[nt][i] = 0.f;

        // S = Q K^T
#pragma unroll
        for (int nt = 0; nt < 7; nt++) {
            mma_f16(sc[nt][0], sc[nt][1], sc[nt][2], sc[nt][3],
                    qa[0][0], qa[0][1], qa[0][2], qa[0][3], kb[nt][0], kb[nt][1]);
            mma_f16(sc[nt][0], sc[nt][1], sc[nt][2], sc[nt][3],
                    qa[1][0], qa[1][1], qa[1][2], qa[1][3], kb[nt][2], kb[nt][3]);
        }

        // scale + bias (mask folded into bias)
#pragma unroll
        for (int nt = 0; nt < 7; nt++) {
            sc[nt][0] = sc[nt][0] * scale + bz0[nt].x;
            sc[nt][1] = sc[nt][1] * scale + bz0[nt].y;
            sc[nt][2] = sc[nt][2] * scale + bz1[nt].x;
            sc[nt][3] = sc[nt][3] * scale + bz1[nt].y;
        }

        // softmax (rows r0, r1)
        float m0 = -1e30f, m1 = -1e30f;
#pragma unroll
        for (int nt = 0; nt < 7; nt++) {
            m0 = fmaxf(m0, fmaxf(sc[nt][0], sc[nt][1]));
            m1 = fmaxf(m1, fmaxf(sc[nt][2], sc[nt][3]));
        }
        m0 = fmaxf(m0, __shfl_xor_sync(0xffffffffu, m0, 1));
        m0 = fmaxf(m0, __shfl_xor_sync(0xffffffffu, m0, 2));
        m1 = fmaxf(m1, __shfl_xor_sync(0xffffffffu, m1, 1));
        m1 = fmaxf(m1, __shfl_xor_sync(0xffffffffu, m1, 2));

        float rs0 = 0.f, rs1 = 0.f;
#pragma unroll
        for (int nt = 0; nt < 7; nt++) {
            sc[nt][0] = __expf(sc[nt][0] - m0); rs0 += sc[nt][0];
            sc[nt][1] = __expf(sc[nt][1] - m0); rs0 += sc[nt][1];
            sc[nt][2] = __expf(sc[nt][2] - m1); rs1 += sc[nt][2];
            sc[nt][3] = __expf(sc[nt][3] - m1); rs1 += sc[nt][3];
        }
        rs0 += __shfl_xor_sync(0xffffffffu, rs0, 1);
        rs0 += __shfl_xor_sync(0xffffffffu, rs0, 2);
        rs1 += __shfl_xor_sync(0xffffffffu, rs1, 1);
        rs1 += __shfl_xor_sync(0xffffffffu, rs1, 2);
        float inv0 = __fdividef(1.f, rs0);
        float inv1 = __fdividef(1.f, rs1);

        // pack P to fp16 A-fragments (C-layout == A-layout identity)
        unsigned pa0[8], pa1[8];
#pragma unroll
        for (int nt = 0; nt < 7; nt++) {
            pa0[nt] = packh2(sc[nt][0], sc[nt][1]);
            pa1[nt] = packh2(sc[nt][2], sc[nt][3]);
        }
        pa0[7] = 0u; pa1[7] = 0u;

        // O = P V   (4 k16 token tiles x 4 n8 dim tiles)
        float oa[4][4];
#pragma unroll
        for (int nt = 0; nt < 4; nt++)
#pragma unroll
            for (int i = 0; i < 4; i++) oa[nt][i] = 0.f;

#pragma unroll
        for (int kt = 0; kt < 4; kt++) {
            unsigned a0 = pa0[2 * kt],     a2 = pa0[2 * kt + 1];
            unsigned a1 = pa1[2 * kt],     a3 = pa1[2 * kt + 1];
#pragma unroll
            for (int dn = 0; dn < 4; dn++) {
                mma_f16(oa[dn][0], oa[dn][1], oa[dn][2], oa[dn][3],
                        a0, a1, a2, a3, vb[dn][2 * kt], vb[dn][2 * kt + 1]);
            }
        }

        // store (normalize by rowsum)
#pragma unroll
        for (int nt = 0; nt < 4; nt++) {
            int col = h * HDIM + nt * 8 + cb;
            if (r0v) {
                float* o = out + ((size_t)b * NTOK + r0) * DIM + col;
                o[0] = oa[nt][0] * inv0;
                o[1] = oa[nt][1] * inv0;
            }
            if (r1v) {
                float* o = out + ((size_t)b * NTOK + r1) * DIM + col;
                o[0] = oa[nt][2] * inv1;
                o[1] = oa[nt][3] * inv1;
            }
        }
    }
}

// ---------------------------------------------------------------------------
// launch
// ---------------------------------------------------------------------------
extern "C" void kernel_launch(void* const* d_in, const int* in_sizes, int n_in,
                              void* d_out, int out_size) {
    const float* X     = (const float*)d_in[0];
    const float* Wq    = (const float*)d_in[1];
    const float* bq    = (const float*)d_in[2];
    const float* Wk    = (const float*)d_in[3];
    const float* bk    = (const float*)d_in[4];
    const float* Wv    = (const float*)d_in[5];
    const float* bv    = (const float*)d_in[6];
    const float* table = (const float*)d_in[7];
    const int*   idx   = (const int*)d_in[8];
    float* out = (float*)d_out;

    cudaFuncSetAttribute(gemm_qkv_f16, cudaFuncAttributeMaxDynamicSharedMemorySize,
                         GSMEM);

    prologue<<<NPRO, 256>>>(X, Wq, Wk, Wv, table, idx);
    gemm_qkv_f16<<<dim3((3 * DIM) / 128, MROWS / 128), 256, GSMEM>>>(bq, bk, bv);
    attn_kernel<<<(BATCH * HEADS) / 4, 128>>>(out);
}

// round 16
// speedup vs baseline: 1.0748x; 1.0274x over previous
#include <cuda_runtime.h>
#include <cuda_fp16.h>
#include <cstdint>
#include <cstddef>

// ---------------------------------------------------------------------------
// Problem constants
// ---------------------------------------------------------------------------
#define BATCH   4096
#define NTOK    49
#define DIM     512
#define HEADS   16
#define HDIM    32
#define MROWS   (BATCH * NTOK)          // 200704 = 1568 * 128 exactly
#define BH      (BATCH * HEADS)         // 65536
#define QK_SZ   ((size_t)BH * NTOK * HDIM)   // 102,760,448 halfs

// Q is pre-scaled by scale*log2e in the GEMM epilogue; the bias table is
// pre-scaled by log2e and stored fp16; softmax then uses bare ex2.
#define LOG2E  1.4426950408889634
#define QSCALE ((float)(0.17677669529663687 * LOG2E))

// fp16 scratch.  NOTE: device globals are zero-initialized at load; the
// V-token padding [49..64) is never written and therefore stays zero, and it
// only ever multiplies P=0 in the attention kernel.  g_k16 carries +512 halfs
// of tail padding because the attention kernel stages K rows [0,56) per bh.
__device__ __align__(16) __half g_q16[QK_SZ];                 // [bh][tok][32]
__device__ __align__(16) __half g_k16[QK_SZ + 512];           // [bh][tok][32]
__device__ __align__(16) __half g_vt16[(size_t)BH * HDIM * 64]; // [bh][d][tok64]
__device__ __align__(16) __half g_x16[(size_t)MROWS * DIM];
__device__ __align__(16) __half g_wt16[3 * DIM * DIM];
// padded bias, log2e-scaled, mask folded in as -inf: [h][64][56]  (fp16)
__device__ __align__(16) __half g_bias[HEADS * 64 * 56];

// ---------------------------------------------------------------------------
// helpers
// ---------------------------------------------------------------------------
__device__ __forceinline__ void mma_f16(float& d0, float& d1, float& d2, float& d3,
                                        unsigned a0, unsigned a1, unsigned a2, unsigned a3,
                                        unsigned b0, unsigned b1) {
    asm volatile(
        "mma.sync.aligned.m16n8k16.row.col.f32.f16.f16.f32 "
        "{%0,%1,%2,%3}, {%4,%5,%6,%7}, {%8,%9}, {%0,%1,%2,%3};"
        : "+f"(d0), "+f"(d1), "+f"(d2), "+f"(d3)
        : "r"(a0), "r"(a1), "r"(a2), "r"(a3), "r"(b0), "r"(b1));
}

__device__ __forceinline__ void ldmx4(unsigned* r, uint32_t addr) {
    asm volatile("ldmatrix.sync.aligned.m8n8.x4.shared.b16 {%0,%1,%2,%3}, [%4];"
                 : "=r"(r[0]), "=r"(r[1]), "=r"(r[2]), "=r"(r[3]) : "r"(addr));
}

__device__ __forceinline__ uint32_t smem_u32(const void* p) {
    return (uint32_t)__cvta_generic_to_shared(p);
}

__device__ __forceinline__ void cp16cg(uint32_t s, const void* g) {
    asm volatile("cp.async.cg.shared.global [%0], [%1], 16;" :: "r"(s), "l"(g));
}

__device__ __forceinline__ unsigned packh2(float a, float b) {
    __half2 h = __floats2half2_rn(a, b);
    return *(unsigned*)&h;
}

__device__ __forceinline__ float ex2f(float x) {
    float r;
    asm("ex2.approx.f32 %0, %1;" : "=f"(r) : "f"(x));
    return r;
}

// ---------------------------------------------------------------------------
// Kernel 1 (FUSED PROLOGUE): one launch does
//   [0, NCONV)            : convert X to fp16 (8 floats / thread)
//   [NCONV, NCONV+768)    : transpose W ([512,512] x3) to fp16, K-contig rows
//   [NCONV+768, +224)     : gather rel-pos bias (log2e-scaled, fp16, -inf mask)
// ---------------------------------------------------------------------------
#define NCONV  ((int)(((size_t)MROWS * DIM) / 2048))   // 50176
#define NTRANS 768                                     // 16*16*3
#define NBIAS  224                                     // 57344/256
#define NPRO   (NCONV + NTRANS + NBIAS)

__global__ __launch_bounds__(256) void prologue(
    const float* __restrict__ X,
    const float* __restrict__ Wq, const float* __restrict__ Wk,
    const float* __restrict__ Wv,
    const float* __restrict__ table, const int* __restrict__ idx) {
    int blk = blockIdx.x;
    if (blk < NCONV) {
        // ---- convert X ----
        size_t i = ((size_t)blk * 256 + threadIdx.x) * 8;
        float4 a = *(const float4*)(X + i);
        float4 b = *(const float4*)(X + i + 4);
        __half2 h0 = __floats2half2_rn(a.x, a.y);
        __half2 h1 = __floats2half2_rn(a.z, a.w);
        __half2 h2 = __floats2half2_rn(b.x, b.y);
        __half2 h3 = __floats2half2_rn(b.z, b.w);
        uint4 o;
        o.x = *(unsigned*)&h0; o.y = *(unsigned*)&h1;
        o.z = *(unsigned*)&h2; o.w = *(unsigned*)&h3;
        *(uint4*)(g_x16 + i) = o;
    } else if (blk < NCONV + NTRANS) {
        // ---- transpose W (32x32 tile, 256 threads = 32x8) ----
        __shared__ float t[32][33];
        int id = blk - NCONV;
        int z = id >> 8;                 // 0..2
        int rem = id & 255;
        int bx = rem & 15, by = rem >> 4;
        const float* W = (z == 0) ? Wq : (z == 1) ? Wk : Wv;
        int tx = threadIdx.x & 31, ty = threadIdx.x >> 5;   // 32 x 8
#pragma unroll
        for (int j = 0; j < 4; j++) {
            int y = ty + j * 8;
            t[y][tx] = W[(by * 32 + y) * DIM + bx * 32 + tx];
        }
        __syncthreads();
#pragma unroll
        for (int j = 0; j < 4; j++) {
            int y = ty + j * 8;          // output row-within-tile
            float v = t[tx][y];
            g_wt16[(size_t)z * DIM * DIM + (size_t)(bx * 32 + y) * DIM
                   + by * 32 + tx] = __float2half_rn(v);
        }
    } else {
        // ---- bias gather (log2e-scaled, fp16, -inf for masked keys) ----
        int t = (blk - NCONV - NTRANS) * 256 + threadIdx.x;
        if (t >= HEADS * 64 * 56) return;
        int h = t / (64 * 56);
        int r = (t / 56) % 64;
        int c = t % 56;
        float v;
        if (c >= NTOK)      v = -__int_as_float(0x7f800000);   // -inf
        else if (r >= NTOK) v = 0.0f;
        else                v = table[idx[r * NTOK + c] * HEADS + h] * (float)LOG2E;
        g_bias[(h * 64 + r) * 56 + c] = __float2half(v);
    }
}

// ---------------------------------------------------------------------------
// Kernel 2: QKV projection GEMM  [200704,512] x [512,1536]  (fp16 HMMA.16816)
//   R5 config (best measured): CTA 128x128, 256 threads, 8 warps 2(M)x4(N),
//   warp tile 64x32, k-chunk 64, 3-stage cp.async, one barrier per chunk.
//   Swizzle: 128B rows of 8 16B chunks; chunk' = chunk ^ (row & 7).
//   Q outputs pre-scaled by scale*log2e for the log2-domain softmax.
// ---------------------------------------------------------------------------
#define STGB 32768                      // A 16KB + B 16KB per stage
#define NSTG 3
#define GSMEM (NSTG * STGB)             // 98304

__global__ __launch_bounds__(256, 2) void gemm_qkv_f16(
    const float* __restrict__ bq, const float* __restrict__ bk,
    const float* __restrict__ bv) {
    extern __shared__ __align__(128) char sm[];
    uint32_t sbase = smem_u32(sm);
    int tid = threadIdx.x;
    int lane = tid & 31, wid = tid >> 5;
    int wm = wid >> 2, wn = wid & 3;
    int lg = lane >> 2, lt = lane & 3;

    int nBase = blockIdx.x * 128;       // 12 N-CTAs share one A M-tile (L2)
    int mBase = blockIdx.y * 128;
    int which = nBase >> 9;             // 0=Q 1=K 2=V
    int nLoc  = nBase & 511;
    const __half* Xs = g_x16 + (size_t)mBase * DIM;
    const __half* Ws = g_wt16 + (size_t)which * DIM * DIM + (size_t)nLoc * DIM;
    const float* bias = (which == 0) ? bq : (which == 1) ? bk : bv;
    float oscale = (which == 0) ? QSCALE : 1.0f;

    float acc[4][4][4];
#pragma unroll
    for (int mt = 0; mt < 4; mt++)
#pragma unroll
        for (int nt = 0; nt < 4; nt++)
#pragma unroll
            for (int i = 0; i < 4; i++) acc[mt][nt][i] = 0.f;

    // one stage = 64 k-columns: A[128][64], B[128][64] fp16, 128B rows
    auto load_stage = [&](int buf, int kc) {
        uint32_t Ab = sbase + buf * STGB;
        uint32_t Bb = Ab + 16384;
#pragma unroll
        for (int i = 0; i < 4; i++) {
            int idx = i * 256 + tid;        // 0..1023
            int r = idx >> 3, c = idx & 7;
            uint32_t dst = r * 128 + ((uint32_t)(c ^ (r & 7))) * 16;
            cp16cg(Ab + dst, Xs + (size_t)r * DIM + kc * 64 + c * 8);
            cp16cg(Bb + dst, Ws + (size_t)r * DIM + kc * 64 + c * 8);
        }
        asm volatile("cp.async.commit_group;" ::: "memory");
    };

    load_stage(0, 0);
    load_stage(1, 1);

    int rA = wm * 64 + (lane & 15);
    int rB = wn * 32 + (lane & 15);
    int cc0 = (lane >> 4);
    int lsw = lane & 7;                 // row&7 == lane&7 for all our ldmatrix

#pragma unroll
    for (int kc = 0; kc < 8; kc++) {
        if (kc < 7) asm volatile("cp.async.wait_group 1;" ::: "memory");
        else        asm volatile("cp.async.wait_group 0;" ::: "memory");
        __syncthreads();
        if (kc + 2 < 8) load_stage((kc + 2) % NSTG, kc + 2);

        uint32_t Ab = sbase + (kc % NSTG) * STGB;
        uint32_t Bb = Ab + 16384;
#pragma unroll
        for (int ks = 0; ks < 4; ks++) {
            uint32_t chunk = (uint32_t)((2 * ks + cc0) ^ lsw);
            unsigned a[4][4];
#pragma unroll
            for (int mt = 0; mt < 4; mt++)
                ldmx4(a[mt], Ab + (rA + mt * 16) * 128 + chunk * 16);
            unsigned bf[2][4];
#pragma unroll
            for (int np = 0; np < 2; np++)
                ldmx4(bf[np], Bb + (rB + np * 16) * 128 + chunk * 16);
#pragma unroll
            for (int mt = 0; mt < 4; mt++) {
#pragma unroll
                for (int nt = 0; nt < 4; nt++) {
                    unsigned b0 = bf[nt >> 1][nt & 1];
                    unsigned b1 = bf[nt >> 1][(nt & 1) + 2];
                    mma_f16(acc[mt][nt][0], acc[mt][nt][1], acc[mt][nt][2], acc[mt][nt][3],
                            a[mt][0], a[mt][1], a[mt][2], a[mt][3], b0, b1);
                }
            }
        }
    }

    // epilogue: bias add (+ Q pre-scale) + fp16 scatter.
    // Q/K -> [bh][tok][32]; V -> transposed [bh][d][64]
#pragma unroll
    for (int mt = 0; mt < 4; mt++) {
#pragma unroll
        for (int nt = 0; nt < 4; nt++) {
            int cc = nLoc + wn * 32 + nt * 8 + 2 * lt;   // column within matrix
            float bv0 = bias[cc], bv1 = bias[cc + 1];
            int h = cc >> 5, d = cc & 31;
            int r0 = mBase + wm * 64 + mt * 16 + lg;
            int r1 = r0 + 8;
            int b0i = r0 / NTOK, tok0 = r0 - b0i * NTOK;
            int b1i = r1 / NTOK, tok1 = r1 - b1i * NTOK;
            float v0 = (acc[mt][nt][0] + bv0) * oscale;
            float v1 = (acc[mt][nt][1] + bv1) * oscale;
            float v2 = (acc[mt][nt][2] + bv0) * oscale;
            float v3 = (acc[mt][nt][3] + bv1) * oscale;
            if (which < 2) {
                __half* base = (which == 0) ? g_q16 : g_k16;
                *(unsigned*)(base + ((size_t)(b0i * HEADS + h) * NTOK + tok0) * HDIM + d)
                    = packh2(v0, v1);
                *(unsigned*)(base + ((size_t)(b1i * HEADS + h) * NTOK + tok1) * HDIM + d)
                    = packh2(v2, v3);
            } else {
                __half* vt0 = g_vt16 + (size_t)(b0i * HEADS + h) * (HDIM * 64);
                __half* vt1 = g_vt16 + (size_t)(b1i * HEADS + h) * (HDIM * 64);
                vt0[d * 64 + tok0]       = __float2half_rn(v0);
                vt0[(d + 1) * 64 + tok0] = __float2half_rn(v1);
                vt1[d * 64 + tok1]       = __float2half_rn(v2);
                vt1[(d + 1) * 64 + tok1] = __float2half_rn(v3);
            }
        }
    }
}

// ---------------------------------------------------------------------------
// Kernel 3: attention (R8 structure; bias-as-accumulator-init, log2 softmax).
//   1 warp = 1 (window, head), 4 warps/CTA.  K/V staged to per-warp smem via
//   cp.async; fragments via ldmatrix.x4 (K stride 80B, Vt 144B, conflict-
//   free).  Q direct gmem (pre-scaled by scale*log2e).  Bias (fp16, log2e-
//   scaled, -inf mask) initializes the S accumulator -> no held bias regs,
//   no scale FMAs.  ex2 softmax.
// ---------------------------------------------------------------------------
#define KS_STRIDE 80                    // 56 rows -> 4480 B
#define VS_STRIDE 144                   // 32 rows -> 4608 B
#define WSMEM (56 * KS_STRIDE + 32 * VS_STRIDE)   // 9088 B per bh

__global__ __launch_bounds__(128) void attn_kernel(float* __restrict__ out) {
    __shared__ __align__(128) char smk[4 * WSMEM];
    int lane = threadIdx.x & 31, wid = threadIdx.x >> 5;
    int bh = blockIdx.x * 4 + wid;
    int b = bh >> 4, h = bh & 15;

    const __half* Q  = g_q16 + (size_t)bh * (NTOK * HDIM);
    const __half* Kg = g_k16 + (size_t)bh * (NTOK * HDIM);
    const __half* Vg = g_vt16 + (size_t)bh * (HDIM * 64);
    const __half* biasH = g_bias + h * 64 * 56;

    uint32_t wbase = smem_u32(smk) + wid * WSMEM;
    uint32_t Ks = wbase;
    uint32_t Vs = wbase + 56 * KS_STRIDE;

    // stage K rows [0,56) (rows 49..55 garbage -> masked by -inf bias) and
    // full Vt [32][64] (token pad zero in gmem).  16B chunks, 15 per lane.
#pragma unroll
    for (int i = 0; i < 7; i++) {       // K: 224 chunks (56 rows x 4)
        int idx = i * 32 + lane;
        cp16cg(Ks + (idx >> 2) * KS_STRIDE + (idx & 3) * 16,
               Kg + (idx >> 2) * HDIM + (idx & 3) * 8);
    }
#pragma unroll
    for (int i = 0; i < 8; i++) {       // V: 256 chunks (32 rows x 8)
        int idx = i * 32 + lane;
        cp16cg(Vs + (idx >> 3) * VS_STRIDE + (idx & 7) * 16,
               Vg + (idx >> 3) * 64 + (idx & 7) * 8);
    }
    asm volatile("cp.async.wait_all;" ::: "memory");
    __syncthreads();

    int lg = lane >> 2;    // 0..7
    int lt = lane & 3;     // 0..3
    int cb = 2 * lt;
    int l7 = lane & 7, l3h = lane >> 3;       // ldmatrix addressing

    // K fragments via ldmatrix: kb[nt][q] = K[nt*8+lg][8q+2lt .. +1]
    unsigned kb[7][4];
#pragma unroll
    for (int nt = 0; nt < 7; nt++)
        ldmx4(kb[nt], Ks + (nt * 8 + l7) * KS_STRIDE + l3h * 16);

    // V fragments via ldmatrix: vb[dn][c] = Vt[dn*8+lg][8c+2lt .. +1]
    unsigned vb[4][8];
#pragma unroll
    for (int dn = 0; dn < 4; dn++) {
        ldmx4(&vb[dn][0], Vs + (dn * 8 + l7) * VS_STRIDE + l3h * 16);
        ldmx4(&vb[dn][4], Vs + (dn * 8 + l7) * VS_STRIDE + l3h * 16 + 64);
    }

#pragma unroll
    for (int mt = 0; mt < 4; mt++) {
        int r0 = mt * 16 + lg;
        int r1 = r0 + 8;
        bool r0v = (r0 < NTOK), r1v = (r1 < NTOK);

        // Q fragments (direct gmem, read-once; pre-scaled by scale*log2e)
        unsigned qa[2][4];
#pragma unroll
        for (int kk = 0; kk < 2; kk++) {
            const __half* q0 = Q + r0 * HDIM + 16 * kk + 2 * lt;
            const __half* q1 = Q + r1 * HDIM + 16 * kk + 2 * lt;
            qa[kk][0] = r0v ? *(const unsigned*)q0 : 0u;
            qa[kk][1] = r1v ? *(const unsigned*)q1 : 0u;
            qa[kk][2] = r0v ? *(const unsigned*)(q0 + 8) : 0u;
            qa[kk][3] = r1v ? *(const unsigned*)(q1 + 8) : 0u;
        }

        // S accumulator initialized with the (log2e-scaled, masked) fp16 bias
        float sc[7][4];
#pragma unroll
        for (int nt = 0; nt < 7; nt++) {
            __half2 u0 = *(const __half2*)(biasH + r0 * 56 + nt * 8 + cb);
            __half2 u1 = *(const __half2*)(biasH + r1 * 56 + nt * 8 + cb);
            float2 f0 = __half22float2(u0);
            float2 f1 = __half22float2(u1);
            sc[nt][0] = f0.x; sc[nt][1] = f0.y;
            sc[nt][2] = f1.x; sc[nt][3] = f1.y;
        }

        // S = Q' K^T + bias'   (log2 domain)
#pragma unroll
        for (int nt = 0; nt < 7; nt++) {
            mma_f16(sc[nt][0], sc[nt][1], sc[nt][2], sc[nt][3],
                    qa[0][0], qa[0][1], qa[0][2], qa[0][3], kb[nt][0], kb[nt][1]);
            mma_f16(sc[nt][0], sc[nt][1], sc[nt][2], sc[nt][3],
                    qa[1][0], qa[1][1], qa[1][2], qa[1][3], kb[nt][2], kb[nt][3]);
        }

        // softmax (rows r0, r1), base-2
        float m0 = -1e30f, m1 = -1e30f;
#pragma unroll
        for (int nt = 0; nt < 7; nt++) {
            m0 = fmaxf(m0, fmaxf(sc[nt][0], sc[nt][1]));
            m1 = fmaxf(m1, fmaxf(sc[nt][2], sc[nt][3]));
        }
        m0 = fmaxf(m0, __shfl_xor_sync(0xffffffffu, m0, 1));
        m0 = fmaxf(m0, __shfl_xor_sync(0xffffffffu, m0, 2));
        m1 = fmaxf(m1, __shfl_xor_sync(0xffffffffu, m1, 1));
        m1 = fmaxf(m1, __shfl_xor_sync(0xffffffffu, m1, 2));

        float rs0 = 0.f, rs1 = 0.f;
#pragma unroll
        for (int nt = 0; nt < 7; nt++) {
            sc[nt][0] = ex2f(sc[nt][0] - m0); rs0 += sc[nt][0];
            sc[nt][1] = ex2f(sc[nt][1] - m0); rs0 += sc[nt][1];
            sc[nt][2] = ex2f(sc[nt][2] - m1); rs1 += sc[nt][2];
            sc[nt][3] = ex2f(sc[nt][3] - m1); rs1 += sc[nt][3];
        }
        rs0 += __shfl_xor_sync(0xffffffffu, rs0, 1);
        rs0 += __shfl_xor_sync(0xffffffffu, rs0, 2);
        rs1 += __shfl_xor_sync(0xffffffffu, rs1, 1);
        rs1 += __shfl_xor_sync(0xffffffffu, rs1, 2);
        float inv0 = __fdividef(1.f, rs0);
        float inv1 = __fdividef(1.f, rs1);

        // pack P to fp16 A-fragments (C-layout == A-layout identity)
        unsigned pa0[8], pa1[8];
#pragma unroll
        for (int nt = 0; nt < 7; nt++) {
            pa0[nt] = packh2(sc[nt][0], sc[nt][1]);
            pa1[nt] = packh2(sc[nt][2], sc[nt][3]);
        }
        pa0[7] = 0u; pa1[7] = 0u;

        // O = P V   (4 k16 token tiles x 4 n8 dim tiles)
        float oa[4][4];
#pragma unroll
        for (int nt = 0; nt < 4; nt++)
#pragma unroll
            for (int i = 0; i < 4; i++) oa[nt][i] = 0.f;

#pragma unroll
        for (int kt = 0; kt < 4; kt++) {
            unsigned a0 = pa0[2 * kt],     a2 = pa0[2 * kt + 1];
            unsigned a1 = pa1[2 * kt],     a3 = pa1[2 * kt + 1];
#pragma unroll
            for (int dn = 0; dn < 4; dn++) {
                mma_f16(oa[dn][0], oa[dn][1], oa[dn][2], oa[dn][3],
                        a0, a1, a2, a3, vb[dn][2 * kt], vb[dn][2 * kt + 1]);
            }
        }

        // store (normalize by rowsum)
#pragma unroll
        for (int nt = 0; nt < 4; nt++) {
            int col = h * HDIM + nt * 8 + cb;
            if (r0v) {
                float* o = out + ((size_t)b * NTOK + r0) * DIM + col;
                o[0] = oa[nt][0] * inv0;
                o[1] = oa[nt][1] * inv0;
            }
            if (r1v) {
                float* o = out + ((size_t)b * NTOK + r1) * DIM + col;
                o[0] = oa[nt][2] * inv1;
                o[1] = oa[nt][3] * inv1;
            }
        }
    }
}

// ---------------------------------------------------------------------------
// launch
// ---------------------------------------------------------------------------
extern "C" void kernel_launch(void* const* d_in, const int* in_sizes, int n_in,
                              void* d_out, int out_size) {
    const float* X     = (const float*)d_in[0];
    const float* Wq    = (const float*)d_in[1];
    const float* bq    = (const float*)d_in[2];
    const float* Wk    = (const float*)d_in[3];
    const float* bk    = (const float*)d_in[4];
    const float* Wv    = (const float*)d_in[5];
    const float* bv    = (const float*)d_in[6];
    const float* table = (const float*)d_in[7];
    const int*   idx   = (const int*)d_in[8];
    float* out = (float*)d_out;

    cudaFuncSetAttribute(gemm_qkv_f16, cudaFuncAttributeMaxDynamicSharedMemorySize,
                         GSMEM);

    prologue<<<NPRO, 256>>>(X, Wq, Wk, Wv, table, idx);
    gemm_qkv_f16<<<dim3((3 * DIM) / 128, MROWS / 128), 256, GSMEM>>>(bq, bk, bv);
    attn_kernel<<<(BATCH * HEADS) / 4, 128>>>(out);
}